// round 5
// baseline (speedup 1.0000x reference)
#include <cuda_runtime.h>
#include <math.h>

// Problem constants
#define B_   32
#define H_   256
#define W_   1216
#define SH_  16
#define SW_  48
#define KH_  30     // int(2*256/17)
#define KW_  49     // int(2*1216/49)
#define HP_  227    // 256-30+1  (valid conv out H)
#define WP_  1168   // 1216-49+1 (valid conv out W)

#define N_SPARSE (B_*H_*W_)               // 9,961,472
#define N_DVT    (B_*H_*W_*2)             // 19,922,944
#define OUT_DVT_OFF   N_SPARSE
#define OUT_GRID_OFF  (N_SPARSE + N_DVT)  // 29,884,416

struct K30 { float v[KH_]; };
struct K49 { float v[KW_]; };

// ---------------------------------------------------------------------------
// ONE kernel, ONE wave. Block = (i:16, b:32), 512 threads, 4 blocks/SM
// => n_conc = 592 >= 512 blocks => all blocks resident simultaneously.
// Block (b,i) owns:
//   - sparse rows [16i, 16i+16) of batch b   -> zero them, scatter into them
//   - dvt rows    [16i, 16i+16) of batch b   -> transpose
//   - sample row i                            -> vconv + hconv + grid + sample
// Scatter row for sample i is 16i+8 +- ~1 => inside owned slice, no races.
// ---------------------------------------------------------------------------
__global__ void __launch_bounds__(512, 4)
k_mega(const float4* __restrict__ dvf4,
       const float* __restrict__ gt,
       float* __restrict__ out,
       K30 GH, K49 GW) {
    int i = blockIdx.x;   // sample row / slice index 0..15
    int b = blockIdx.y;   // batch
    int t = threadIdx.x;  // 0..511

    __shared__ float row[2][W_];

    // ---- vertical Gaussian pass: 30-tap dot per (ch,w4) column task ------
    // 608 tasks strip-mined over 512 threads (threads 0..95 do two).
    {
        int h0 = (i * HP_) >> 4;   // i*227/16
        for (int task = t; task < 608; task += 512) {
            int ch = task >= 304;
            int w4 = ch ? (task - 304) : task;
            const float4* src = dvf4 + (((size_t)(b * 2 + ch) * H_) + h0) * 304 + w4;
            float4 acc = make_float4(0.f, 0.f, 0.f, 0.f);
#pragma unroll
            for (int r = 0; r < KH_; r++) {
                float4 v = src[r * 304];
                float  w = GH.v[r];
                acc.x += w * v.x; acc.y += w * v.y; acc.z += w * v.z; acc.w += w * v.w;
            }
            *reinterpret_cast<float4*>(&row[ch][4 * w4]) = acc;
        }
    }

    // ---- transpose slice: dvf [b][c][16i+r][:] -> dvt [b][16i+r][:][c] ---
    // float4 loads: 16 rows x 304 float4 per channel = 4864 load-pairs,
    // each producing two interleaved float4 outputs.
    {
        const float4* c0 = dvf4 + (((size_t)(b * 2 + 0) * H_) + 16 * i) * 304;
        const float4* c1 = dvf4 + (((size_t)(b * 2 + 1) * H_) + 16 * i) * 304;
        float4* dst = reinterpret_cast<float4*>(out + OUT_DVT_OFF)
                      + (((size_t)b * H_) + 16 * i) * 608;
        for (int idx = t; idx < 16 * 304; idx += 512) {
            float4 a = c0[idx];
            float4 c = c1[idx];
            __stcs(&dst[2 * idx + 0], make_float4(a.x, c.x, a.y, c.y));
            __stcs(&dst[2 * idx + 1], make_float4(a.z, c.z, a.w, c.w));
        }
    }

    // ---- zero owned sparse rows: 16 rows x 304 float4 = 4864 float4 ------
    {
        float4* z = reinterpret_cast<float4*>(out)
                    + (((size_t)b * H_) + 16 * i) * 304;
        const float4 zero4 = make_float4(0.f, 0.f, 0.f, 0.f);
        for (int k = t; k < 4864; k += 512) __stcs(&z[k], zero4);
    }

    __syncthreads();

    // ---- horizontal pass + epilogue: one thread per sample column j ------
    if (t < SW_) {
        int j = t;
        int w0 = (j * WP_) / SW_;
        float ax = 0.f, ay = 0.f;
#pragma unroll
        for (int s = 0; s < KW_; s++) {
            float w = GW.v[s];
            ax += w * row[0][w0 + s];
            ay += w * row[1][w0 + s];
        }
        float gx = ax + (2.0f * (float)j - 47.0f) * (1.0f / 48.0f);
        float gy = ay + (2.0f * (float)i - 15.0f) * (1.0f / 16.0f);
        reinterpret_cast<float2*>(out + OUT_GRID_OFF)[(b * SH_ + i) * SW_ + j]
            = make_float2(gx, gy);

        // bilinear grid_sample (zeros padding, align_corners=False)
        float x = (gx + 1.0f) * ((float)W_ * 0.5f) - 0.5f;
        float y = (gy + 1.0f) * ((float)H_ * 0.5f) - 0.5f;
        float x0f = floorf(x), y0f = floorf(y);
        int x0 = (int)x0f, y0 = (int)y0f;
        int x1 = x0 + 1,   y1 = y0 + 1;
        float wx1 = x - x0f, wx0 = 1.0f - wx1;
        float wy1 = y - y0f, wy0 = 1.0f - wy1;

        const float* gtb = gt + (size_t)b * (H_ * W_);
        float v00 = 0.f, v01 = 0.f, v10 = 0.f, v11 = 0.f;
        bool yok0 = (y0 >= 0) && (y0 < H_);
        bool yok1 = (y1 >= 0) && (y1 < H_);
        bool xok0 = (x0 >= 0) && (x0 < W_);
        bool xok1 = (x1 >= 0) && (x1 < W_);
        if (yok0 && xok0) v00 = gtb[y0 * W_ + x0];
        if (yok0 && xok1) v01 = gtb[y0 * W_ + x1];
        if (yok1 && xok0) v10 = gtb[y1 * W_ + x0];
        if (yok1 && xok1) v11 = gtb[y1 * W_ + x1];
        float val = wy0 * wx0 * v00 + wy0 * wx1 * v01
                  + wy1 * wx0 * v10 + wy1 * wx1 * v11;

        // scatter (truncation matches astype(int32) after the clip)
        float rf = (gy + 1.0f) * 0.5f * (float)H_;
        float cf = (gx + 1.0f) * 0.5f * (float)W_;
        int rI = (int)rf;  rI = rI < 0 ? 0 : (rI > H_ - 1 ? H_ - 1 : rI);
        int cI = (int)cf;  cI = cI < 0 ? 0 : (cI > W_ - 1 ? W_ - 1 : cI);
        if (rI >= 96) out[((size_t)b * H_ + rI) * W_ + cI] = val;
    }
}

// ---------------------------------------------------------------------------
extern "C" void kernel_launch(void* const* d_in, const int* in_sizes, int n_in,
                              void* d_out, int out_size) {
    const float* gt  = (const float*)d_in[0];
    const float* dvf = (const float*)d_in[1];
    float* out = (float*)d_out;

    // Gaussian weights in double, normalized per-axis (separable equivalent of
    // k = outer(gh,gw)/k.sum()).
    K30 GH; K49 GW;
    {
        double sh = (2.0 * (double)H_ / (double)(SH_ + 1)) / 3.0;  // 512/17/3
        double sw = (2.0 * (double)W_ / (double)(SW_ + 1)) / 3.0;  // 2432/49/3
        double g[KW_], s;
        s = 0.0;
        for (int r = 0; r < KH_; r++) {
            double u = ((double)r - (double)(KH_ - 1) / 2.0) / sh;
            g[r] = exp(-u * u / 2.0);
            s += g[r];
        }
        for (int r = 0; r < KH_; r++) GH.v[r] = (float)(g[r] / s);
        s = 0.0;
        for (int c = 0; c < KW_; c++) {
            double u = ((double)c - (double)(KW_ - 1) / 2.0) / sw;
            g[c] = exp(-u * u / 2.0);
            s += g[c];
        }
        for (int c = 0; c < KW_; c++) GW.v[c] = (float)(g[c] / s);
    }

    k_mega<<<dim3(SH_, B_), 512>>>((const float4*)dvf, gt, out, GH, GW);
}

// round 6
// speedup vs baseline: 1.0032x; 1.0032x over previous
#include <cuda_runtime.h>
#include <math.h>

// Problem constants
#define B_   32
#define H_   256
#define W_   1216
#define SH_  16
#define SW_  48
#define KH_  30     // int(2*256/17)
#define KW_  49     // int(2*1216/49)
#define HP_  227    // 256-30+1  (valid conv out H)
#define WP_  1168   // 1216-49+1 (valid conv out W)

#define N_SPARSE (B_*H_*W_)               // 9,961,472
#define N_DVT    (B_*H_*W_*2)             // 19,922,944
#define OUT_DVT_OFF   N_SPARSE
#define OUT_GRID_OFF  (N_SPARSE + N_DVT)  // 29,884,416

struct K30 { float v[KH_]; };
struct K49 { float v[KW_]; };

// ---------------------------------------------------------------------------
// ONE kernel, ONE wave. Block = (i:16, b:32), 512 threads, 4 blocks/SM.
// Block (b,i) owns sparse rows / dvt rows [16i,16i+16) of batch b and
// sample row i. Scatter row is 16i+8 +- ~1 => no inter-block races.
// ---------------------------------------------------------------------------
__global__ void __launch_bounds__(512, 4)
k_mega(const float4* __restrict__ dvf4,
       const float2* __restrict__ dvf2,
       const float* __restrict__ gt,
       float* __restrict__ out,
       K30 GH, K49 GW) {
    int i = blockIdx.x;   // sample row / slice index 0..15
    int b = blockIdx.y;   // batch
    int t = threadIdx.x;  // 0..511

    __shared__ float row[2][W_];

    // ---- transpose slice FIRST (also warms L2 for the vconv window) ------
    // dvf [b][c][16i+r][:] -> dvt [b][16i+r][:][c]
    // 16 rows x 608 float2-pairs = 9728 tasks = 512 threads x 19.
    // Batched 4-wide: 8 independent 8B loads in flight per thread (16 regs).
    {
        const int NT = 16 * 608;  // 9728
        const float2* c0 = dvf2 + (((size_t)(b * 2 + 0) * H_) + 16 * i) * 608;
        const float2* c1 = dvf2 + (((size_t)(b * 2 + 1) * H_) + 16 * i) * 608;
        float4* dst = reinterpret_cast<float4*>(out + OUT_DVT_OFF)
                      + (((size_t)b * H_) + 16 * i) * 608;
        int idx = t;
#pragma unroll 1
        for (int rep = 0; rep < 4; rep++) {   // 4 reps x 4 lanes = 16 iters
            float2 a0 = c0[idx];          float2 q0 = c1[idx];
            float2 a1 = c0[idx + 512];    float2 q1 = c1[idx + 512];
            float2 a2 = c0[idx + 1024];   float2 q2 = c1[idx + 1024];
            float2 a3 = c0[idx + 1536];   float2 q3 = c1[idx + 1536];
            __stcs(&dst[idx],        make_float4(a0.x, q0.x, a0.y, q0.y));
            __stcs(&dst[idx + 512],  make_float4(a1.x, q1.x, a1.y, q1.y));
            __stcs(&dst[idx + 1024], make_float4(a2.x, q2.x, a2.y, q2.y));
            __stcs(&dst[idx + 1536], make_float4(a3.x, q3.x, a3.y, q3.y));
            idx += 2048;
        }
        // remainder: 3 more iters (16 + 3 = 19); idx = t + 8192 here
        {
            float2 a0 = c0[idx];          float2 q0 = c1[idx];
            float2 a1 = c0[idx + 512];    float2 q1 = c1[idx + 512];
            float2 a2 = c0[idx + 1024];   float2 q2 = c1[idx + 1024];
            __stcs(&dst[idx],        make_float4(a0.x, q0.x, a0.y, q0.y));
            __stcs(&dst[idx + 512],  make_float4(a1.x, q1.x, a1.y, q1.y));
            __stcs(&dst[idx + 1024], make_float4(a2.x, q2.x, a2.y, q2.y));
            (void)NT;
        }
    }

    // ---- vertical Gaussian pass: 30-tap dot per (ch,w4) column task ------
    {
        int h0 = (i * HP_) >> 4;   // i*227/16
        for (int task = t; task < 608; task += 512) {
            int ch = task >= 304;
            int w4 = ch ? (task - 304) : task;
            const float4* src = dvf4 + (((size_t)(b * 2 + ch) * H_) + h0) * 304 + w4;
            float4 acc = make_float4(0.f, 0.f, 0.f, 0.f);
#pragma unroll
            for (int r = 0; r < KH_; r++) {
                float4 v = src[r * 304];
                float  w = GH.v[r];
                acc.x += w * v.x; acc.y += w * v.y; acc.z += w * v.z; acc.w += w * v.w;
            }
            *reinterpret_cast<float4*>(&row[ch][4 * w4]) = acc;
        }
    }

    // ---- zero owned sparse rows: 16 rows x 304 float4 = 4864 float4 ------
    {
        float4* z = reinterpret_cast<float4*>(out)
                    + (((size_t)b * H_) + 16 * i) * 304;
        const float4 zero4 = make_float4(0.f, 0.f, 0.f, 0.f);
        for (int k = t; k < 4864; k += 512) __stcs(&z[k], zero4);
    }

    __syncthreads();

    // ---- horizontal pass + epilogue: one thread per sample column j ------
    if (t < SW_) {
        int j = t;
        int w0 = (j * WP_) / SW_;
        float ax = 0.f, ay = 0.f;
#pragma unroll
        for (int s = 0; s < KW_; s++) {
            float w = GW.v[s];
            ax += w * row[0][w0 + s];
            ay += w * row[1][w0 + s];
        }
        float gx = ax + (2.0f * (float)j - 47.0f) * (1.0f / 48.0f);
        float gy = ay + (2.0f * (float)i - 15.0f) * (1.0f / 16.0f);
        reinterpret_cast<float2*>(out + OUT_GRID_OFF)[(b * SH_ + i) * SW_ + j]
            = make_float2(gx, gy);

        // bilinear grid_sample (zeros padding, align_corners=False)
        float x = (gx + 1.0f) * ((float)W_ * 0.5f) - 0.5f;
        float y = (gy + 1.0f) * ((float)H_ * 0.5f) - 0.5f;
        float x0f = floorf(x), y0f = floorf(y);
        int x0 = (int)x0f, y0 = (int)y0f;
        int x1 = x0 + 1,   y1 = y0 + 1;
        float wx1 = x - x0f, wx0 = 1.0f - wx1;
        float wy1 = y - y0f, wy0 = 1.0f - wy1;

        const float* gtb = gt + (size_t)b * (H_ * W_);
        float v00 = 0.f, v01 = 0.f, v10 = 0.f, v11 = 0.f;
        bool yok0 = (y0 >= 0) && (y0 < H_);
        bool yok1 = (y1 >= 0) && (y1 < H_);
        bool xok0 = (x0 >= 0) && (x0 < W_);
        bool xok1 = (x1 >= 0) && (x1 < W_);
        if (yok0 && xok0) v00 = gtb[y0 * W_ + x0];
        if (yok0 && xok1) v01 = gtb[y0 * W_ + x1];
        if (yok1 && xok0) v10 = gtb[y1 * W_ + x0];
        if (yok1 && xok1) v11 = gtb[y1 * W_ + x1];
        float val = wy0 * wx0 * v00 + wy0 * wx1 * v01
                  + wy1 * wx0 * v10 + wy1 * wx1 * v11;

        // scatter (truncation matches astype(int32) after the clip)
        float rf = (gy + 1.0f) * 0.5f * (float)H_;
        float cf = (gx + 1.0f) * 0.5f * (float)W_;
        int rI = (int)rf;  rI = rI < 0 ? 0 : (rI > H_ - 1 ? H_ - 1 : rI);
        int cI = (int)cf;  cI = cI < 0 ? 0 : (cI > W_ - 1 ? W_ - 1 : cI);
        if (rI >= 96) out[((size_t)b * H_ + rI) * W_ + cI] = val;
    }
}

// ---------------------------------------------------------------------------
extern "C" void kernel_launch(void* const* d_in, const int* in_sizes, int n_in,
                              void* d_out, int out_size) {
    const float* gt  = (const float*)d_in[0];
    const float* dvf = (const float*)d_in[1];
    float* out = (float*)d_out;

    // Gaussian weights in double, normalized per-axis (separable equivalent of
    // k = outer(gh,gw)/k.sum()).
    K30 GH; K49 GW;
    {
        double sh = (2.0 * (double)H_ / (double)(SH_ + 1)) / 3.0;  // 512/17/3
        double sw = (2.0 * (double)W_ / (double)(SW_ + 1)) / 3.0;  // 2432/49/3
        double g[KW_], s;
        s = 0.0;
        for (int r = 0; r < KH_; r++) {
            double u = ((double)r - (double)(KH_ - 1) / 2.0) / sh;
            g[r] = exp(-u * u / 2.0);
            s += g[r];
        }
        for (int r = 0; r < KH_; r++) GH.v[r] = (float)(g[r] / s);
        s = 0.0;
        for (int c = 0; c < KW_; c++) {
            double u = ((double)c - (double)(KW_ - 1) / 2.0) / sw;
            g[c] = exp(-u * u / 2.0);
            s += g[c];
        }
        for (int c = 0; c < KW_; c++) GW.v[c] = (float)(g[c] / s);
    }

    k_mega<<<dim3(SH_, B_), 512>>>((const float4*)dvf, (const float2*)dvf,
                                   gt, out, GH, GW);
}

// round 7
// speedup vs baseline: 1.1412x; 1.1375x over previous
#include <cuda_runtime.h>
#include <math.h>

// Problem constants
#define B_   32
#define H_   256
#define W_   1216
#define SH_  16
#define SW_  48
#define KH_  30     // int(2*256/17)
#define KW_  49     // int(2*1216/49)
#define HP_  227    // 256-30+1  (valid conv out H)
#define WP_  1168   // 1216-49+1 (valid conv out W)

#define N_SPARSE (B_*H_*W_)               // 9,961,472
#define N_DVT    (B_*H_*W_*2)             // 19,922,944
#define OUT_DVT_OFF   N_SPARSE
#define OUT_GRID_OFF  (N_SPARSE + N_DVT)  // 29,884,416

struct K30 { float v[KH_]; };
struct K49 { float v[KW_]; };

// ---------------------------------------------------------------------------
// ONE kernel, ONE wave. Block = (i:16, b:32), 512 threads, 4 blocks/SM.
// Block (b,i) owns sparse rows / dvt rows [16i,16i+16) of batch b and
// sample row i. Scatter row is 16i+8 +- ~1 => no inter-block races.
// Order matters: vconv reads the 30-row window first; the transpose then
// re-reads 16 of those rows from L2 (saves ~35 MB of DRAM reads).
// ---------------------------------------------------------------------------
__global__ void __launch_bounds__(512, 4)
k_mega(const float4* __restrict__ dvf4,
       const float2* __restrict__ dvf2,
       const float* __restrict__ gt,
       float* __restrict__ out,
       K30 GH, K49 GW) {
    int i = blockIdx.x;   // sample row / slice index 0..15
    int b = blockIdx.y;   // batch
    int t = threadIdx.x;  // 0..511

    __shared__ float row[2][W_];

    // ---- vertical Gaussian pass: 30-tap dot per (ch,w4) column task ------
    // 608 tasks strip-mined over 512 threads (threads 0..95 do two).
    {
        int h0 = (i * HP_) >> 4;   // i*227/16
        for (int task = t; task < 608; task += 512) {
            int ch = task >= 304;
            int w4 = ch ? (task - 304) : task;
            const float4* src = dvf4 + (((size_t)(b * 2 + ch) * H_) + h0) * 304 + w4;
            float4 acc = make_float4(0.f, 0.f, 0.f, 0.f);
#pragma unroll
            for (int r = 0; r < KH_; r++) {
                float4 v = src[r * 304];
                float  w = GH.v[r];
                acc.x += w * v.x; acc.y += w * v.y; acc.z += w * v.z; acc.w += w * v.w;
            }
            *reinterpret_cast<float4*>(&row[ch][4 * w4]) = acc;
        }
    }

    // ---- transpose slice: dvf [b][c][16i+r][:] -> dvt [b][16i+r][:][c] ---
    // 16 rows x 608 float2-pairs = 9728 tasks = 512 threads x 19 iters.
    // Batched 4-wide: 8 independent 8B loads in flight per thread.
    {
        const float2* c0 = dvf2 + (((size_t)(b * 2 + 0) * H_) + 16 * i) * 608;
        const float2* c1 = dvf2 + (((size_t)(b * 2 + 1) * H_) + 16 * i) * 608;
        float4* dst = reinterpret_cast<float4*>(out + OUT_DVT_OFF)
                      + (((size_t)b * H_) + 16 * i) * 608;
        int idx = t;
#pragma unroll 1
        for (int rep = 0; rep < 4; rep++) {   // 4 reps x 4 lanes = 16 iters
            float2 a0 = c0[idx];          float2 q0 = c1[idx];
            float2 a1 = c0[idx + 512];    float2 q1 = c1[idx + 512];
            float2 a2 = c0[idx + 1024];   float2 q2 = c1[idx + 1024];
            float2 a3 = c0[idx + 1536];   float2 q3 = c1[idx + 1536];
            __stcs(&dst[idx],        make_float4(a0.x, q0.x, a0.y, q0.y));
            __stcs(&dst[idx + 512],  make_float4(a1.x, q1.x, a1.y, q1.y));
            __stcs(&dst[idx + 1024], make_float4(a2.x, q2.x, a2.y, q2.y));
            __stcs(&dst[idx + 1536], make_float4(a3.x, q3.x, a3.y, q3.y));
            idx += 2048;
        }
        // remainder: 3 more iters (16 + 3 = 19); idx = t + 8192 here
        {
            float2 a0 = c0[idx];          float2 q0 = c1[idx];
            float2 a1 = c0[idx + 512];    float2 q1 = c1[idx + 512];
            float2 a2 = c0[idx + 1024];   float2 q2 = c1[idx + 1024];
            __stcs(&dst[idx],        make_float4(a0.x, q0.x, a0.y, q0.y));
            __stcs(&dst[idx + 512],  make_float4(a1.x, q1.x, a1.y, q1.y));
            __stcs(&dst[idx + 1024], make_float4(a2.x, q2.x, a2.y, q2.y));
        }
    }

    // ---- zero owned sparse rows: 16 rows x 304 float4 = 4864 float4 ------
    {
        float4* z = reinterpret_cast<float4*>(out)
                    + (((size_t)b * H_) + 16 * i) * 304;
        const float4 zero4 = make_float4(0.f, 0.f, 0.f, 0.f);
        for (int k = t; k < 4864; k += 512) __stcs(&z[k], zero4);
    }

    __syncthreads();

    // ---- horizontal pass + epilogue: one thread per sample column j ------
    if (t < SW_) {
        int j = t;
        int w0 = (j * WP_) / SW_;
        float ax = 0.f, ay = 0.f;
#pragma unroll
        for (int s = 0; s < KW_; s++) {
            float w = GW.v[s];
            ax += w * row[0][w0 + s];
            ay += w * row[1][w0 + s];
        }
        float gx = ax + (2.0f * (float)j - 47.0f) * (1.0f / 48.0f);
        float gy = ay + (2.0f * (float)i - 15.0f) * (1.0f / 16.0f);
        reinterpret_cast<float2*>(out + OUT_GRID_OFF)[(b * SH_ + i) * SW_ + j]
            = make_float2(gx, gy);

        // bilinear grid_sample (zeros padding, align_corners=False)
        float x = (gx + 1.0f) * ((float)W_ * 0.5f) - 0.5f;
        float y = (gy + 1.0f) * ((float)H_ * 0.5f) - 0.5f;
        float x0f = floorf(x), y0f = floorf(y);
        int x0 = (int)x0f, y0 = (int)y0f;
        int x1 = x0 + 1,   y1 = y0 + 1;
        float wx1 = x - x0f, wx0 = 1.0f - wx1;
        float wy1 = y - y0f, wy0 = 1.0f - wy1;

        const float* gtb = gt + (size_t)b * (H_ * W_);
        float v00 = 0.f, v01 = 0.f, v10 = 0.f, v11 = 0.f;
        bool yok0 = (y0 >= 0) && (y0 < H_);
        bool yok1 = (y1 >= 0) && (y1 < H_);
        bool xok0 = (x0 >= 0) && (x0 < W_);
        bool xok1 = (x1 >= 0) && (x1 < W_);
        if (yok0 && xok0) v00 = gtb[y0 * W_ + x0];
        if (yok0 && xok1) v01 = gtb[y0 * W_ + x1];
        if (yok1 && xok0) v10 = gtb[y1 * W_ + x0];
        if (yok1 && xok1) v11 = gtb[y1 * W_ + x1];
        float val = wy0 * wx0 * v00 + wy0 * wx1 * v01
                  + wy1 * wx0 * v10 + wy1 * wx1 * v11;

        // scatter (truncation matches astype(int32) after the clip)
        float rf = (gy + 1.0f) * 0.5f * (float)H_;
        float cf = (gx + 1.0f) * 0.5f * (float)W_;
        int rI = (int)rf;  rI = rI < 0 ? 0 : (rI > H_ - 1 ? H_ - 1 : rI);
        int cI = (int)cf;  cI = cI < 0 ? 0 : (cI > W_ - 1 ? W_ - 1 : cI);
        if (rI >= 96) out[((size_t)b * H_ + rI) * W_ + cI] = val;
    }
}

// ---------------------------------------------------------------------------
extern "C" void kernel_launch(void* const* d_in, const int* in_sizes, int n_in,
                              void* d_out, int out_size) {
    const float* gt  = (const float*)d_in[0];
    const float* dvf = (const float*)d_in[1];
    float* out = (float*)d_out;

    // Gaussian weights in double, normalized per-axis (separable equivalent of
    // k = outer(gh,gw)/k.sum()).
    K30 GH; K49 GW;
    {
        double sh = (2.0 * (double)H_ / (double)(SH_ + 1)) / 3.0;  // 512/17/3
        double sw = (2.0 * (double)W_ / (double)(SW_ + 1)) / 3.0;  // 2432/49/3
        double g[KW_], s;
        s = 0.0;
        for (int r = 0; r < KH_; r++) {
            double u = ((double)r - (double)(KH_ - 1) / 2.0) / sh;
            g[r] = exp(-u * u / 2.0);
            s += g[r];
        }
        for (int r = 0; r < KH_; r++) GH.v[r] = (float)(g[r] / s);
        s = 0.0;
        for (int c = 0; c < KW_; c++) {
            double u = ((double)c - (double)(KW_ - 1) / 2.0) / sw;
            g[c] = exp(-u * u / 2.0);
            s += g[c];
        }
        for (int c = 0; c < KW_; c++) GW.v[c] = (float)(g[c] / s);
    }

    k_mega<<<dim3(SH_, B_), 512>>>((const float4*)dvf, (const float2*)dvf,
                                   gt, out, GH, GW);
}